// round 16
// baseline (speedup 1.0000x reference)
#include <cuda_runtime.h>
#include <cuda_bf16.h>
#include <math.h>
#include <stdint.h>

#define S_LEN 1024
#define BATCH 2
#define DM    1024
#define NH    16
#define DH    64
#define CC    32
#define MROWS (S_LEN*BATCH)
#define QSCALE 0.125f
#define NCH   32
#define CS    32

__device__ float g_scratch[29 * 1024 * 1024];

#define MB (1024*1024)
#define OFF_QU   ((size_t)0)
#define OFF_KD   ((size_t)2*MB)
#define OFF_VDK  ((size_t)6*MB)
#define OFF_VDV  ((size_t)8*MB)
#define OFF_DOWN ((size_t)12*MB)
#define OFF_W    ((size_t)13*MB)
#define OFF_STK  ((size_t)14*MB)
#define OFF_STV  ((size_t)16*MB)
#define OFF_STN  ((size_t)18*MB)
#define OFF_XH   ((size_t)19*MB)
#define OFF_XL   ((size_t)20*MB)
#define OFF_WQH  ((size_t)21*MB)
#define OFF_WQL  ((size_t)(21*MB+MB/2))
#define OFF_WKH  ((size_t)22*MB)
#define OFF_WKL  ((size_t)(22*MB+MB/2))
#define OFF_WVH  ((size_t)23*MB)
#define OFF_WVL  ((size_t)(23*MB+MB/2))
#define OFF_WOH  ((size_t)24*MB)
#define OFF_WOL  ((size_t)(24*MB+MB/2))
#define OFF_VDH  ((size_t)25*MB)
#define OFF_VDL  ((size_t)26*MB)
#define OFF_ATH  ((size_t)27*MB)
#define OFF_ATL  ((size_t)28*MB)

__device__ __forceinline__ uint32_t smem_addr_u32(const void* p) {
    uint32_t a;
    asm("{ .reg .u64 t; cvta.to.shared.u64 t, %1; cvt.u32.u64 %0, t; }"
        : "=r"(a) : "l"(p));
    return a;
}

#define LDM4(r, addr)                                                         \
    asm volatile("ldmatrix.sync.aligned.m8n8.x4.shared.b16 {%0,%1,%2,%3}, [%4];" \
        : "=r"((r)[0]), "=r"((r)[1]), "=r"((r)[2]), "=r"((r)[3])              \
        : "r"(addr))

#define MMA16816(d, a, b0, b1)                                                \
    asm volatile(                                                             \
        "mma.sync.aligned.m16n8k16.row.col.f32.bf16.bf16.f32 "                \
        "{%0,%1,%2,%3}, {%4,%5,%6,%7}, {%8,%9}, {%0,%1,%2,%3};"               \
        : "+f"((d)[0]), "+f"((d)[1]), "+f"((d)[2]), "+f"((d)[3])              \
        : "r"((a)[0]), "r"((a)[1]), "r"((a)[2]), "r"((a)[3]),                 \
          "r"(b0), "r"(b1))

#define CP16(dst, src)                                                        \
    asm volatile("cp.async.cg.shared.global [%0], [%1], 16;"                  \
        :: "r"(dst), "l"((size_t)__cvta_generic_to_global(src)) : "memory")
#define CP_COMMIT() asm volatile("cp.async.commit_group;" ::: "memory")
#define CP_WAIT2()  asm volatile("cp.async.wait_group 2;"  ::: "memory")

__device__ __forceinline__ uint32_t pack_bf16(float x, float y) {
    __nv_bfloat16 a = __float2bfloat16(x), b = __float2bfloat16(y);
    return (uint32_t)__bfloat16_as_ushort(a) |
           ((uint32_t)__bfloat16_as_ushort(b) << 16);
}

__device__ __forceinline__ void cvt_body(const float4* src, uint2* hi,
                                         uint2* lo, int i)
{
    float4 v = src[i];
    __nv_bfloat16 a = __float2bfloat16(v.x), b = __float2bfloat16(v.y),
                  c = __float2bfloat16(v.z), d = __float2bfloat16(v.w);
    uint2 h, l;
    h.x = (uint32_t)__bfloat16_as_ushort(a) | ((uint32_t)__bfloat16_as_ushort(b) << 16);
    h.y = (uint32_t)__bfloat16_as_ushort(c) | ((uint32_t)__bfloat16_as_ushort(d) << 16);
    l.x = pack_bf16(v.x - __bfloat162float(a), v.y - __bfloat162float(b));
    l.y = pack_bf16(v.z - __bfloat162float(c), v.w - __bfloat162float(d));
    hi[i] = h;
    lo[i] = l;
}

struct CvtSeg { const float4* src; uint2* hi; uint2* lo; int n4; };

__global__ __launch_bounds__(256) void cvt_multi_kernel(
    CvtSeg s0, CvtSeg s1, CvtSeg s2, CvtSeg s3, CvtSeg s4)
{
    CvtSeg s = (blockIdx.y == 0) ? s0 : (blockIdx.y == 1) ? s1 :
               (blockIdx.y == 2) ? s2 : (blockIdx.y == 3) ? s3 : s4;
    int i = blockIdx.x * 256 + threadIdx.x;
    if (i < s.n4) cvt_body(s.src, s.hi, s.lo, i);
}

/* ================================================================== */
/* HMMA GEMM NT + bias: 64x128 tile, 256 thr, 3-stage, 2 CTAs/SM.      */
/* ================================================================== */
#define RS      80
#define PA      (64*RS)
#define PB      (128*RS)
#define STG_B   (2*PA + 2*PB)
#define GEMM_SMEM (3*STG_B)

struct GemmArgs {
    const __nv_bfloat16* Bh;
    const __nv_bfloat16* Bl;
    const float*         bias;
    float*               C;
    __nv_bfloat16*       outH;
    __nv_bfloat16*       outL;
};

__device__ __forceinline__ void issue_stage(
    uint32_t sdst, const __nv_bfloat16* Ah, const __nv_bfloat16* Al,
    const __nv_bfloat16* Bh, const __nv_bfloat16* Bl,
    int bm, int bn, int k0, int tid)
{
    {
        const int r = tid >> 2, seg = tid & 3;
        const size_t ga = (size_t)(bm + r) * DM + k0 + seg * 8;
        const uint32_t d = sdst + (uint32_t)(r * RS + seg * 16);
        CP16(d,      Ah + ga);
        CP16(d + PA, Al + ga);
    }
    #pragma unroll
    for (int i = 0; i < 2; i++) {
        const int idx = tid * 2 + i;
        const int r = idx >> 2, seg = idx & 3;
        const size_t gb = (size_t)(bn + r) * DM + k0 + seg * 8;
        const uint32_t d = sdst + (uint32_t)(2*PA + r * RS + seg * 16);
        CP16(d,      Bh + gb);
        CP16(d + PB, Bl + gb);
    }
}

__global__ __launch_bounds__(256, 2) void gemm_bf16_bias(
    const __nv_bfloat16* __restrict__ Ah, const __nv_bfloat16* __restrict__ Al,
    GemmArgs a0, GemmArgs a1, GemmArgs a2)
{
    extern __shared__ __align__(16) char sm[];
    const uint32_t sbase = smem_addr_u32(sm);
    const int tid = threadIdx.x, lane = tid & 31, w = tid >> 5;
    const int wm = w & 1, wn = w >> 1;
    const int bm = blockIdx.y * 64, bn = blockIdx.x * 128;
    const GemmArgs ar = (blockIdx.z == 0) ? a0 : (blockIdx.z == 1) ? a1 : a2;
    const __nv_bfloat16* Bh = ar.Bh;
    const __nv_bfloat16* Bl = ar.Bl;

    float acc[2][4][4];
    #pragma unroll
    for (int i = 0; i < 2; i++)
        #pragma unroll
        for (int j = 0; j < 4; j++)
            #pragma unroll
            for (int k = 0; k < 4; k++) acc[i][j][k] = 0.f;

    const uint32_t aRel = (uint32_t)((wm * 32 + (lane & 15)) * RS + (lane >> 4) * 16);
    const uint32_t bRel = (uint32_t)(2*PA + (wn * 32 + (lane & 7) + ((lane >> 4) & 1) * 8) * RS
                                     + ((lane >> 3) & 1) * 16);

    #pragma unroll
    for (int s = 0; s < 3; s++) {
        issue_stage(sbase + s * STG_B, Ah, Al, Bh, Bl, bm, bn, s * 32, tid);
        CP_COMMIT();
    }

    int buf = 0;
    for (int kt = 0; kt < 32; ++kt) {
        CP_WAIT2();
        __syncthreads();

        const uint32_t so = sbase + (uint32_t)buf * STG_B;
        #pragma unroll
        for (int ks = 0; ks < 2; ++ks) {
            uint32_t ah[2][4], al[2][4], bh[2][4], bl[2][4];
            #pragma unroll
            for (int mt = 0; mt < 2; mt++) {
                const uint32_t off = aRel + (uint32_t)(mt * 16 * RS + ks * 32);
                LDM4(ah[mt], so + off);
                LDM4(al[mt], so + PA + off);
            }
            #pragma unroll
            for (int g = 0; g < 2; g++) {
                const uint32_t off = bRel + (uint32_t)(g * 16 * RS + ks * 32);
                LDM4(bh[g], so + off);
                LDM4(bl[g], so + PB + off);
            }
            #pragma unroll
            for (int mt = 0; mt < 2; mt++)
                #pragma unroll
                for (int nt = 0; nt < 4; nt++) {
                    const int g = nt >> 1, p = (nt & 1) * 2;
                    MMA16816(acc[mt][nt], ah[mt], bh[g][p], bh[g][p + 1]);
                }
            #pragma unroll
            for (int mt = 0; mt < 2; mt++)
                #pragma unroll
                for (int nt = 0; nt < 4; nt++) {
                    const int g = nt >> 1, p = (nt & 1) * 2;
                    MMA16816(acc[mt][nt], al[mt], bh[g][p], bh[g][p + 1]);
                }
            #pragma unroll
            for (int mt = 0; mt < 2; mt++)
                #pragma unroll
                for (int nt = 0; nt < 4; nt++) {
                    const int g = nt >> 1, p = (nt & 1) * 2;
                    MMA16816(acc[mt][nt], ah[mt], bl[g][p], bl[g][p + 1]);
                }
        }

        __syncthreads();
        if (kt + 3 < 32)
            issue_stage(sbase + (uint32_t)buf * STG_B, Ah, Al, Bh, Bl,
                        bm, bn, (kt + 3) * 32, tid);
        CP_COMMIT();
        buf = (buf == 2) ? 0 : buf + 1;
    }

    const float* bias = ar.bias;
    #pragma unroll
    for (int mt = 0; mt < 2; mt++) {
        const int r0 = bm + wm * 32 + mt * 16 + (lane >> 2);
        #pragma unroll
        for (int nt = 0; nt < 4; nt++) {
            const int c0 = bn + wn * 32 + nt * 8 + (lane & 3) * 2;
            const float b0 = bias[c0], b1 = bias[c0 + 1];
            const float v00 = acc[mt][nt][0] + b0, v01 = acc[mt][nt][1] + b1;
            const float v10 = acc[mt][nt][2] + b0, v11 = acc[mt][nt][3] + b1;
            if (ar.C) {
                *(float2*)&ar.C[(size_t)r0 * DM + c0]       = make_float2(v00, v01);
                *(float2*)&ar.C[(size_t)(r0 + 8) * DM + c0] = make_float2(v10, v11);
            }
            if (ar.outH) {
                __nv_bfloat16 h00 = __float2bfloat16(v00), h01 = __float2bfloat16(v01);
                __nv_bfloat16 h10 = __float2bfloat16(v10), h11 = __float2bfloat16(v11);
                *(uint32_t*)&ar.outH[(size_t)r0 * DM + c0] =
                    (uint32_t)__bfloat16_as_ushort(h00) |
                    ((uint32_t)__bfloat16_as_ushort(h01) << 16);
                *(uint32_t*)&ar.outL[(size_t)r0 * DM + c0] =
                    pack_bf16(v00 - __bfloat162float(h00), v01 - __bfloat162float(h01));
                *(uint32_t*)&ar.outH[(size_t)(r0 + 8) * DM + c0] =
                    (uint32_t)__bfloat16_as_ushort(h10) |
                    ((uint32_t)__bfloat16_as_ushort(h11) << 16);
                *(uint32_t*)&ar.outL[(size_t)(r0 + 8) * DM + c0] =
                    pack_bf16(v10 - __bfloat162float(h10), v11 - __bfloat162float(h11));
            }
        }
    }
}

/* ------------------------------------------------------------------ */
__global__ __launch_bounds__(128) void down_kernel(
    const float* __restrict__ q_down, const float* __restrict__ kd,
    float* __restrict__ down)
{
    const int bh = blockIdx.y;
    const int b  = bh >> 4;
    const int h  = bh & 15;
    const int s  = blockIdx.x * 128 + threadIdx.x;

    __shared__ float qd[CC][DH];
    for (int i = threadIdx.x; i < CC * DH; i += 128) {
        int c = i >> 6, d = i & 63;
        qd[c][d] = q_down[c * DM + h * DH + d] * QSCALE;
    }
    __syncthreads();

    const float* kp = kd + (size_t)s * (BATCH * DM) + b * DM + h * DH;
    float kr[DH];
    #pragma unroll
    for (int d = 0; d < DH; d++) kr[d] = kp[d];

    #pragma unroll 4
    for (int c = 0; c < CC; c++) {
        float acc = 0.f;
        #pragma unroll
        for (int d = 0; d < DH; d++) acc += qd[c][d] * kr[d];
        down[((size_t)bh * CC + c) * S_LEN + s] = acc;
    }
}

__global__ __launch_bounds__(128) void maxexp_kernel(
    const float* __restrict__ down, float* __restrict__ wmat)
{
    const int bc = blockIdx.x;
    const int bh = bc >> 5;
    const int c  = bc & 31;
    const int t  = threadIdx.x;
    const float* row = down + (size_t)bc * S_LEN;

    float mx = -3.0e38f;
    for (int i = t; i < S_LEN; i += 128) mx = fmaxf(mx, row[i]);

    __shared__ float red[128];
    red[t] = mx;
    __syncthreads();
    for (int st = 64; st > 0; st >>= 1) {
        if (t < st) red[t] = fmaxf(red[t], red[t + st]);
        __syncthreads();
    }
    mx = red[0];

    for (int i = t; i < S_LEN; i += 128)
        wmat[((size_t)bh * S_LEN + i) * CC + c] = __expf(row[i] - mx);
}

__global__ __launch_bounds__(256) void chunk_sum_kernel(
    const float* __restrict__ vk, const float* __restrict__ vv,
    const float* __restrict__ wmat,
    float* __restrict__ stK, float* __restrict__ stV, float* __restrict__ stN)
{
    const int bc = blockIdx.x;
    const int bh = bc >> 5, ch = bc & 31;
    const int b  = bh >> 4, h = bh & 15;
    const int tid = threadIdx.x, lane = tid & 31, warp = tid >> 5;
    const int s0 = ch * CS;

    __shared__ float vks[CS][DH];
    __shared__ float vvs[CS][DH];
    __shared__ float ws[CS][CC];

    const size_t base_off = (size_t)b * DM + h * DH;

    for (int i = tid; i < CS * DH; i += 256) {
        int r = i >> 6, d = i & 63;
        size_t g = (size_t)(s0 + r) * (BATCH * DM) + base_off + d;
        vks[r][d] = vk[g];
        vvs[r][d] = vv[g];
    }
    for (int i = tid; i < CS * CC; i += 256) {
        int r = i >> 5, c = i & 31;
        ws[r][c] = wmat[((size_t)bh * S_LEN + s0 + r) * CC + c];
    }
    __syncthreads();

    float Ak[8], Av[8];
    #pragma unroll
    for (int j = 0; j < 8; j++) { Ak[j] = 0.f; Av[j] = 0.f; }
    float norm = 0.f;
    for (int i = 0; i < CS; i++) {
        const float wvv = ws[i][lane];
        norm += wvv;
        #pragma unroll
        for (int j = 0; j < 8; j++) {
            Ak[j] += wvv * vks[i][warp * 8 + j];
            Av[j] += wvv * vvs[i][warp * 8 + j];
        }
    }

    const size_t so = ((size_t)bh * NCH + ch) * 2048 + lane * 64 + warp * 8;
    #pragma unroll
    for (int j = 0; j < 8; j++) { stK[so + j] = Ak[j]; stV[so + j] = Av[j]; }
    if (warp == 0) stN[((size_t)bh * NCH + ch) * 32 + lane] = norm;
}

__global__ __launch_bounds__(256) void scan_kernel(
    float* __restrict__ stK, float* __restrict__ stV, float* __restrict__ stN)
{
    const int bh = blockIdx.x, part = blockIdx.y, tid = threadIdx.x;
    if (part < 16) {
        float* base = ((part < 8) ? stK : stV) + (size_t)bh * NCH * 2048;
        const int idx = (part & 7) * 256 + tid;
        float a = 0.f;
        #pragma unroll
        for (int j = 0; j < NCH; j++) {
            float t = base[j * 2048 + idx];
            base[j * 2048 + idx] = a;
            a += t;
        }
    } else if (tid < 32) {
        float* bN = stN + (size_t)bh * NCH * 32;
        float a = 0.f;
        #pragma unroll
        for (int j = 0; j < NCH; j++) {
            float t = bN[j * 32 + tid]; bN[j * 32 + tid] = a; a += t;
        }
    }
}

#define TP36 36
#define DP68 68
#define O_Q    0
#define O_VKT  2080
#define O_VVS  4384
#define O_AKT  6560
#define O_AVS  8864
#define O_W    11040
#define O_WT   12192
#define O_P    13344
#define O_C    14496
#define O_NC   15648
#define O_N0   16800
#define ACH_SMEM ((O_N0 + 32) * 4)

__global__ __launch_bounds__(256) void attn_chunk_kernel(
    const float* __restrict__ qu, const float* __restrict__ vkm,
    const float* __restrict__ vvm, const float* __restrict__ wmat,
    const float* __restrict__ stK, const float* __restrict__ stV,
    const float* __restrict__ stN,
    __nv_bfloat16* __restrict__ ath, __nv_bfloat16* __restrict__ atl)
{
    extern __shared__ float sh[];
    const int bc = blockIdx.x, bh = bc >> 5, ch = bc & 31;
    const int b = bh >> 4, h = bh & 15;
    const int tid = threadIdx.x;
    const int s0 = ch * CS;
    const size_t base = (size_t)b * DM + h * DH;

    for (int i = tid; i < 32 * 64; i += 256) {
        int r = i >> 6, d = i & 63;
        size_t g = (size_t)(s0 + r) * (BATCH * DM) + base + d;
        sh[O_Q   + r * 65 + d]   = qu[g] * QSCALE;
        sh[O_VKT + d * TP36 + r] = vkm[g];
        sh[O_VVS + r * DP68 + d] = vvm[g];
    }
    const size_t st0 = ((size_t)bh * NCH + ch) * 2048;
    for (int i = tid; i < 32 * 64; i += 256) {
        int c = i >> 6, d = i & 63;
        sh[O_AKT + d * TP36 + c] = stK[st0 + i];
        sh[O_AVS + c * DP68 + d] = stV[st0 + i];
    }
    for (int i = tid; i < 32 * 32; i += 256) {
        int r = i >> 5, c = i & 31;
        float wv = wmat[((size_t)bh * S_LEN + s0 + r) * CC + c];
        sh[O_W  + r * TP36 + c] = wv;
        sh[O_WT + c * TP36 + r] = wv;
    }
    if (tid < 32) sh[O_N0 + tid] = stN[((size_t)bh * NCH + ch) * 32 + tid];
    __syncthreads();

    const int s  = tid >> 3;
    const int q4 = (tid & 7) * 4;

    if (tid < 32) {
        float run = sh[O_N0 + tid];
        for (int ss = 0; ss < 32; ss++) {
            run += sh[O_W + ss * TP36 + tid];
            sh[O_NC + ss * TP36 + tid] = run;
        }
    }

    {
        float c0 = 0, c1 = 0, c2 = 0, c3 = 0;
        #pragma unroll 8
        for (int d = 0; d < 64; d++) {
            const float a = sh[O_Q + s * 65 + d];
            const float4 bv = *(const float4*)&sh[O_VKT + d * TP36 + q4];
            c0 += a * bv.x; c1 += a * bv.y; c2 += a * bv.z; c3 += a * bv.w;
        }
        sh[O_P + s * TP36 + q4 + 0] = (q4 + 0 <= s) ? c0 : 0.f;
        sh[O_P + s * TP36 + q4 + 1] = (q4 + 1 <= s) ? c1 : 0.f;
        sh[O_P + s * TP36 + q4 + 2] = (q4 + 2 <= s) ? c2 : 0.f;
        sh[O_P + s * TP36 + q4 + 3] = (q4 + 3 <= s) ? c3 : 0.f;
    }
    __syncthreads();

    {
        float c0 = 0, c1 = 0, c2 = 0, c3 = 0;
        #pragma unroll 8
        for (int d = 0; d < 64; d++) {
            const float a = sh[O_Q + s * 65 + d];
            const float4 bv = *(const float4*)&sh[O_AKT + d * TP36 + q4];
            c0 += a * bv.x; c1 += a * bv.y; c2 += a * bv.z; c3 += a * bv.w;
        }
        #pragma unroll 8
        for (int t = 0; t < 32; t++) {
            const float a = sh[O_P + s * TP36 + t];
            const float4 bv = *(const float4*)&sh[O_W + t * TP36 + q4];
            c0 += a * bv.x; c1 += a * bv.y; c2 += a * bv.z; c3 += a * bv.w;
        }
        const float4 nc = *(const float4*)&sh[O_NC + s * TP36 + q4];
        sh[O_C + s * TP36 + q4 + 0] = c0 / nc.x;
        sh[O_C + s * TP36 + q4 + 1] = c1 / nc.y;
        sh[O_C + s * TP36 + q4 + 2] = c2 / nc.z;
        sh[O_C + s * TP36 + q4 + 3] = c3 / nc.w;
    }
    __syncthreads();

    {
        const int lane = tid & 31, w = tid >> 5;
        #pragma unroll
        for (int r = w * 4; r < w * 4 + 4; r++) {
            float v = sh[O_C + r * TP36 + lane];
            float mx = v;
            #pragma unroll
            for (int o = 16; o > 0; o >>= 1)
                mx = fmaxf(mx, __shfl_xor_sync(0xFFFFFFFFu, mx, o));
            float e = __expf(v - mx);
            float se = e;
            #pragma unroll
            for (int o = 16; o > 0; o >>= 1)
                se += __shfl_xor_sync(0xFFFFFFFFu, se, o);
            sh[O_C + r * TP36 + lane] = e / (se * sh[O_NC + r * TP36 + lane]);
        }
    }
    __syncthreads();

    {
        float c0 = 0, c1 = 0, c2 = 0, c3 = 0;
        #pragma unroll 8
        for (int c = 0; c < 32; c++) {
            const float a = sh[O_C + s * TP36 + c];
            const float4 bv = *(const float4*)&sh[O_WT + c * TP36 + q4];
            c0 += a * bv.x; c1 += a * bv.y; c2 += a * bv.z; c3 += a * bv.w;
        }
        sh[O_P + s * TP36 + q4 + 0] = (q4 + 0 <= s) ? c0 : 0.f;
        sh[O_P + s * TP36 + q4 + 1] = (q4 + 1 <= s) ? c1 : 0.f;
        sh[O_P + s * TP36 + q4 + 2] = (q4 + 2 <= s) ? c2 : 0.f;
        sh[O_P + s * TP36 + q4 + 3] = (q4 + 3 <= s) ? c3 : 0.f;
    }
    __syncthreads();

    #pragma unroll
    for (int half = 0; half < 2; half++) {
        const int dd = q4 + half * 32;
        float o0 = 0, o1 = 0, o2 = 0, o3 = 0;
        #pragma unroll 8
        for (int c = 0; c < 32; c++) {
            const float a = sh[O_C + s * TP36 + c];
            const float4 bv = *(const float4*)&sh[O_AVS + c * DP68 + dd];
            o0 += a * bv.x; o1 += a * bv.y; o2 += a * bv.z; o3 += a * bv.w;
        }
        #pragma unroll 8
        for (int t = 0; t < 32; t++) {
            const float g = sh[O_P + s * TP36 + t];
            const float4 bv = *(const float4*)&sh[O_VVS + t * DP68 + dd];
            o0 += g * bv.x; o1 += g * bv.y; o2 += g * bv.z; o3 += g * bv.w;
        }
        const size_t gi = (size_t)(s0 + s) * (BATCH * DM) + base + dd;
        float vals[4] = {o0, o1, o2, o3};
        #pragma unroll
        for (int j = 0; j < 4; j++) {
            __nv_bfloat16 hb = __float2bfloat16(vals[j]);
            ath[gi + j] = hb;
            atl[gi + j] = __float2bfloat16(vals[j] - __bfloat162float(hb));
        }
    }
}

/* ------------------------------------------------------------------ */
extern "C" void kernel_launch(void* const* d_in, const int* in_sizes, int n_in,
                              void* d_out, int out_size)
{
    (void)in_sizes; (void)n_in; (void)out_size;
    const float* x      = (const float*)d_in[0];
    const float* q_down = (const float*)d_in[1];
    const float* Wq     = (const float*)d_in[2];
    const float* bq     = (const float*)d_in[3];
    const float* Wk     = (const float*)d_in[4];
    const float* bk     = (const float*)d_in[5];
    const float* Wv     = (const float*)d_in[6];
    const float* bv     = (const float*)d_in[7];
    const float* Wo     = (const float*)d_in[8];
    const float* bo     = (const float*)d_in[9];
    float* out = (float*)d_out;

    float* scr = nullptr;
    cudaGetSymbolAddress((void**)&scr, g_scratch);
    float* g_qu  = scr + OFF_QU;
    float* g_kd  = scr + OFF_KD;
    float* g_vdk = scr + OFF_VDK;
    float* g_vdv = scr + OFF_VDV;
    float* g_dn  = scr + OFF_DOWN;
    float* g_w   = scr + OFF_W;
    float* g_stk = scr + OFF_STK;
    float* g_stv = scr + OFF_STV;
    float* g_stn = scr + OFF_STN;

    __nv_bfloat16* xh  = (__nv_bfloat16*)(scr + OFF_XH);
    __nv_bfloat16* xl  = (__nv_bfloat16*)(scr + OFF_XL);
    __nv_bfloat16* wqh = (__nv_bfloat16*)(scr + OFF_WQH);
    __nv_bfloat16* wql = (__nv_bfloat16*)(scr + OFF_WQL);
    __nv_bfloat16* wkh = (__nv_bfloat16*)(scr + OFF_WKH);
    __nv_bfloat16* wkl = (__nv_bfloat16*)(scr + OFF_WKL);
    __nv_bfloat16* wvh = (__nv_bfloat16*)(scr + OFF_WVH);
    __nv_bfloat16* wvl = (__nv_bfloat16*)(scr + OFF_WVL);
    __nv_bfloat16* woh = (__nv_bfloat16*)(scr + OFF_WOH);
    __nv_bfloat16* wol = (__nv_bfloat16*)(scr + OFF_WOL);
    __nv_bfloat16* vdh = (__nv_bfloat16*)(scr + OFF_VDH);
    __nv_bfloat16* vdl = (__nv_bfloat16*)(scr + OFF_VDL);
    __nv_bfloat16* ath = (__nv_bfloat16*)(scr + OFF_ATH);
    __nv_bfloat16* atl = (__nv_bfloat16*)(scr + OFF_ATL);

    cudaFuncSetAttribute(gemm_bf16_bias,
                         cudaFuncAttributeMaxDynamicSharedMemorySize, GEMM_SMEM);
    cudaFuncSetAttribute(attn_chunk_kernel,
                         cudaFuncAttributeMaxDynamicSharedMemorySize, ACH_SMEM);

    const int n4x = MROWS * DM / 4;
    const int n4w = DM * DM / 4;

    CvtSeg cs0 = {(const float4*)x,  (uint2*)xh,  (uint2*)xl,  n4x};
    CvtSeg cs1 = {(const float4*)Wq, (uint2*)wqh, (uint2*)wql, n4w};
    CvtSeg cs2 = {(const float4*)Wk, (uint2*)wkh, (uint2*)wkl, n4w};
    CvtSeg cs3 = {(const float4*)Wv, (uint2*)wvh, (uint2*)wvl, n4w};
    CvtSeg cs4 = {(const float4*)Wo, (uint2*)woh, (uint2*)wol, n4w};
    cvt_multi_kernel<<<dim3(n4x / 256, 5), 256>>>(cs0, cs1, cs2, cs3, cs4);

    GemmArgs aq  = {wqh, wql, bq, g_qu,   nullptr, nullptr};
    GemmArgs ak  = {wkh, wkl, bk, g_kd,   nullptr, nullptr};
    GemmArgs av  = {wvh, wvl, bv, nullptr, vdh, vdl};     /* vd: planes only */
    GemmArgs a2k = {wkh, wkl, bk, g_vdk,  nullptr, nullptr};
    GemmArgs a2v = {wvh, wvl, bv, g_vdv,  nullptr, nullptr};
    GemmArgs ao  = {woh, wol, bo, out,    nullptr, nullptr};

    dim3 gg(DM / 128, MROWS / 64);   /* (8, 32) */

    gemm_bf16_bias<<<dim3(gg.x, gg.y, 3), 256, GEMM_SMEM>>>(xh, xl, aq, ak, av);

    gemm_bf16_bias<<<dim3(gg.x, gg.y, 2), 256, GEMM_SMEM>>>(vdh, vdl, a2k, a2v, a2v);

    down_kernel<<<dim3(S_LEN / 128, BATCH * NH), 128>>>(q_down, g_kd, g_dn);
    maxexp_kernel<<<BATCH * NH * CC, 128>>>(g_dn, g_w);

    chunk_sum_kernel<<<BATCH * NH * NCH, 256>>>(g_vdk, g_vdv, g_w,
                                                g_stk, g_stv, g_stn);
    scan_kernel<<<dim3(BATCH * NH, 17), 256>>>(g_stk, g_stv, g_stn);
    attn_chunk_kernel<<<BATCH * NH * NCH, 256, ACH_SMEM>>>(
        g_qu, g_vdk, g_vdv, g_w, g_stk, g_stv, g_stn, ath, atl);

    gemm_bf16_bias<<<dim3(gg.x, gg.y, 1), 256, GEMM_SMEM>>>(ath, atl, ao, ao, ao);
}

// round 17
// speedup vs baseline: 1.7241x; 1.7241x over previous
#include <cuda_runtime.h>
#include <cuda_bf16.h>
#include <math.h>
#include <stdint.h>

#define S_LEN 1024
#define BATCH 2
#define DM    1024
#define NH    16
#define DH    64
#define CC    32
#define MROWS (S_LEN*BATCH)
#define QSCALE 0.125f
#define NCH   32
#define CS    32

__device__ float g_scratch[29 * 1024 * 1024];

#define MB (1024*1024)
#define OFF_QU   ((size_t)0)
#define OFF_KD   ((size_t)2*MB)
#define OFF_VDK  ((size_t)6*MB)
#define OFF_VDV  ((size_t)8*MB)
#define OFF_DOWN ((size_t)12*MB)
#define OFF_W    ((size_t)13*MB)
#define OFF_STK  ((size_t)14*MB)
#define OFF_STV  ((size_t)16*MB)
#define OFF_STN  ((size_t)18*MB)
#define OFF_XH   ((size_t)19*MB)
#define OFF_XL   ((size_t)20*MB)
#define OFF_WQH  ((size_t)21*MB)
#define OFF_WQL  ((size_t)(21*MB+MB/2))
#define OFF_WKH  ((size_t)22*MB)
#define OFF_WKL  ((size_t)(22*MB+MB/2))
#define OFF_WVH  ((size_t)23*MB)
#define OFF_WVL  ((size_t)(23*MB+MB/2))
#define OFF_WOH  ((size_t)24*MB)
#define OFF_WOL  ((size_t)(24*MB+MB/2))
#define OFF_VDH  ((size_t)25*MB)
#define OFF_VDL  ((size_t)26*MB)
#define OFF_ATH  ((size_t)27*MB)
#define OFF_ATL  ((size_t)28*MB)

/* ================================================================== */
/* helpers                                                             */
/* ================================================================== */
__device__ __forceinline__ uint32_t smem_addr_u32(const void* p) {
    uint32_t a;
    asm("{ .reg .u64 t; cvta.to.shared.u64 t, %1; cvt.u32.u64 %0, t; }"
        : "=r"(a) : "l"(p));
    return a;
}

#define LDM4(r, addr)                                                         \
    asm volatile("ldmatrix.sync.aligned.m8n8.x4.shared.b16 {%0,%1,%2,%3}, [%4];" \
        : "=r"((r)[0]), "=r"((r)[1]), "=r"((r)[2]), "=r"((r)[3])              \
        : "r"(addr))

#define MMA16816(d, a, b0, b1)                                                \
    asm volatile(                                                             \
        "mma.sync.aligned.m16n8k16.row.col.f32.bf16.bf16.f32 "                \
        "{%0,%1,%2,%3}, {%4,%5,%6,%7}, {%8,%9}, {%0,%1,%2,%3};"               \
        : "+f"((d)[0]), "+f"((d)[1]), "+f"((d)[2]), "+f"((d)[3])              \
        : "r"((a)[0]), "r"((a)[1]), "r"((a)[2]), "r"((a)[3]),                 \
          "r"(b0), "r"(b1))

#define CP16(dst, src)                                                        \
    asm volatile("cp.async.cg.shared.global [%0], [%1], 16;"                  \
        :: "r"(dst), "l"((size_t)__cvta_generic_to_global(src)) : "memory")
#define CP_COMMIT() asm volatile("cp.async.commit_group;" ::: "memory")
#define CP_WAIT2()  asm volatile("cp.async.wait_group 2;"  ::: "memory")

__device__ __forceinline__ uint32_t pack_bf16(float x, float y) {
    __nv_bfloat16 a = __float2bfloat16(x), b = __float2bfloat16(y);
    return (uint32_t)__bfloat16_as_ushort(a) |
           ((uint32_t)__bfloat16_as_ushort(b) << 16);
}

/* ================================================================== */
/* fp32 -> (hi, lo) bf16 planes                                        */
/* ================================================================== */
__device__ __forceinline__ void cvt_body(const float4* src, uint2* hi,
                                         uint2* lo, int i)
{
    float4 v = src[i];
    __nv_bfloat16 a = __float2bfloat16(v.x), b = __float2bfloat16(v.y),
                  c = __float2bfloat16(v.z), d = __float2bfloat16(v.w);
    uint2 h, l;
    h.x = (uint32_t)__bfloat16_as_ushort(a) | ((uint32_t)__bfloat16_as_ushort(b) << 16);
    h.y = (uint32_t)__bfloat16_as_ushort(c) | ((uint32_t)__bfloat16_as_ushort(d) << 16);
    l.x = pack_bf16(v.x - __bfloat162float(a), v.y - __bfloat162float(b));
    l.y = pack_bf16(v.z - __bfloat162float(c), v.w - __bfloat162float(d));
    hi[i] = h;
    lo[i] = l;
}

struct CvtSeg { const float4* src; uint2* hi; uint2* lo; int n4; };

__global__ __launch_bounds__(256) void cvt_multi_kernel(
    CvtSeg s0, CvtSeg s1, CvtSeg s2, CvtSeg s3, CvtSeg s4)
{
    CvtSeg s = (blockIdx.y == 0) ? s0 : (blockIdx.y == 1) ? s1 :
               (blockIdx.y == 2) ? s2 : (blockIdx.y == 3) ? s3 : s4;
    int i = blockIdx.x * 256 + threadIdx.x;
    if (i < s.n4) cvt_body(s.src, s.hi, s.lo, i);
}

/* ================================================================== */
/* HMMA GEMM NT + bias — R12 configuration (best measured):            */
/* 128x128 tile, 512 threads, 16 warps (32x32), 4-stage cp.async.      */
/* Epilogue writes fp32 C and/or bf16 hi/lo planes.                    */
/* ================================================================== */
#define RS      80
#define PART_B  (128*RS)
#define STG_B   (4*PART_B)
#define NSTAGE  4
#define GEMM_SMEM (NSTAGE*STG_B)   /* 163840 */

struct GemmArgs {
    const __nv_bfloat16* Bh;
    const __nv_bfloat16* Bl;
    const float*         bias;
    float*               C;      /* may be null */
    __nv_bfloat16*       outH;   /* may be null */
    __nv_bfloat16*       outL;
};

__device__ __forceinline__ void issue_stage(
    uint32_t sdst, const __nv_bfloat16* Ah, const __nv_bfloat16* Al,
    const __nv_bfloat16* Bh, const __nv_bfloat16* Bl,
    int bm, int bn, int k0, int tid)
{
    const int r = tid >> 2, seg = tid & 3;
    const size_t ga = (size_t)(bm + r) * DM + k0 + seg * 8;
    const size_t gb = (size_t)(bn + r) * DM + k0 + seg * 8;
    const uint32_t d = sdst + (uint32_t)(r * RS + seg * 16);
    CP16(d,            Ah + ga);
    CP16(d + PART_B,   Al + ga);
    CP16(d + 2*PART_B, Bh + gb);
    CP16(d + 3*PART_B, Bl + gb);
}

__global__ __launch_bounds__(512, 1) void gemm_bf16_bias(
    const __nv_bfloat16* __restrict__ Ah, const __nv_bfloat16* __restrict__ Al,
    GemmArgs a0, GemmArgs a1, GemmArgs a2)
{
    extern __shared__ __align__(16) char sm[];
    const uint32_t sbase = smem_addr_u32(sm);
    const int tid = threadIdx.x, lane = tid & 31, w = tid >> 5;
    const int wm = w & 3, wn = w >> 2;           /* 4x4 warp grid */
    const int bm = blockIdx.y * 128, bn = blockIdx.x * 128;
    const GemmArgs ar = (blockIdx.z == 0) ? a0 : (blockIdx.z == 1) ? a1 : a2;
    const __nv_bfloat16* Bh = ar.Bh;
    const __nv_bfloat16* Bl = ar.Bl;

    float acc[2][4][4];
    #pragma unroll
    for (int i = 0; i < 2; i++)
        #pragma unroll
        for (int j = 0; j < 4; j++)
            #pragma unroll
            for (int k = 0; k < 4; k++) acc[i][j][k] = 0.f;

    const uint32_t aRel = (uint32_t)((wm * 32 + (lane & 15)) * RS + (lane >> 4) * 16);
    const uint32_t bRel = (uint32_t)((wn * 32 + (lane & 7) + ((lane >> 4) & 1) * 8) * RS
                                     + ((lane >> 3) & 1) * 16);

    #pragma unroll
    for (int s = 0; s < 3; s++) {
        issue_stage(sbase + s * STG_B, Ah, Al, Bh, Bl, bm, bn, s * 32, tid);
        CP_COMMIT();
    }

    for (int kt = 0; kt < 32; ++kt) {
        CP_WAIT2();
        __syncthreads();

        if (kt + 3 < 32)
            issue_stage(sbase + ((kt + 3) & 3) * STG_B, Ah, Al, Bh, Bl,
                        bm, bn, (kt + 3) * 32, tid);
        CP_COMMIT();

        const uint32_t so = sbase + (uint32_t)(kt & 3) * STG_B;
        #pragma unroll
        for (int ks = 0; ks < 2; ++ks) {
            uint32_t ah[2][4], al[2][4], bh[2][4], bl[2][4];
            #pragma unroll
            for (int mt = 0; mt < 2; mt++) {
                const uint32_t off = aRel + (uint32_t)(mt * 16 * RS + ks * 32);
                LDM4(ah[mt], so + off);
                LDM4(al[mt], so + PART_B + off);
            }
            #pragma unroll
            for (int g = 0; g < 2; g++) {
                const uint32_t off = bRel + (uint32_t)(g * 16 * RS + ks * 32);
                LDM4(bh[g], so + 2*PART_B + off);
                LDM4(bl[g], so + 3*PART_B + off);
            }
            /* product-major: 8 independent accs between reuse */
            #pragma unroll
            for (int mt = 0; mt < 2; mt++)
                #pragma unroll
                for (int nt = 0; nt < 4; nt++) {
                    const int g = nt >> 1, p = (nt & 1) * 2;
                    MMA16816(acc[mt][nt], ah[mt], bh[g][p], bh[g][p + 1]);
                }
            #pragma unroll
            for (int mt = 0; mt < 2; mt++)
                #pragma unroll
                for (int nt = 0; nt < 4; nt++) {
                    const int g = nt >> 1, p = (nt & 1) * 2;
                    MMA16816(acc[mt][nt], al[mt], bh[g][p], bh[g][p + 1]);
                }
            #pragma unroll
            for (int mt = 0; mt < 2; mt++)
                #pragma unroll
                for (int nt = 0; nt < 4; nt++) {
                    const int g = nt >> 1, p = (nt & 1) * 2;
                    MMA16816(acc[mt][nt], ah[mt], bl[g][p], bl[g][p + 1]);
                }
        }
    }

    const float* bias = ar.bias;
    #pragma unroll
    for (int mt = 0; mt < 2; mt++) {
        const int r0 = bm + wm * 32 + mt * 16 + (lane >> 2);
        #pragma unroll
        for (int nt = 0; nt < 4; nt++) {
            const int c0 = bn + wn * 32 + nt * 8 + (lane & 3) * 2;
            const float b0 = bias[c0], b1 = bias[c0 + 1];
            const float v00 = acc[mt][nt][0] + b0, v01 = acc[mt][nt][1] + b1;
            const float v10 = acc[mt][nt][2] + b0, v11 = acc[mt][nt][3] + b1;
            if (ar.C) {
                *(float2*)&ar.C[(size_t)r0 * DM + c0]       = make_float2(v00, v01);
                *(float2*)&ar.C[(size_t)(r0 + 8) * DM + c0] = make_float2(v10, v11);
            }
            if (ar.outH) {
                __nv_bfloat16 h00 = __float2bfloat16(v00), h01 = __float2bfloat16(v01);
                __nv_bfloat16 h10 = __float2bfloat16(v10), h11 = __float2bfloat16(v11);
                *(uint32_t*)&ar.outH[(size_t)r0 * DM + c0] =
                    (uint32_t)__bfloat16_as_ushort(h00) |
                    ((uint32_t)__bfloat16_as_ushort(h01) << 16);
                *(uint32_t*)&ar.outL[(size_t)r0 * DM + c0] =
                    pack_bf16(v00 - __bfloat162float(h00), v01 - __bfloat162float(h01));
                *(uint32_t*)&ar.outH[(size_t)(r0 + 8) * DM + c0] =
                    (uint32_t)__bfloat16_as_ushort(h10) |
                    ((uint32_t)__bfloat16_as_ushort(h11) << 16);
                *(uint32_t*)&ar.outL[(size_t)(r0 + 8) * DM + c0] =
                    pack_bf16(v10 - __bfloat162float(h10), v11 - __bfloat162float(h11));
            }
        }
    }
}

/* ------------------------------------------------------------------ */
/* down[bh][c][s] — 4-way c-split, 512 threads (latency fix).          */
/* ------------------------------------------------------------------ */
__global__ __launch_bounds__(512) void down_kernel(
    const float* __restrict__ q_down, const float* __restrict__ kd,
    float* __restrict__ down)
{
    const int bh = blockIdx.y;
    const int b  = bh >> 4;
    const int h  = bh & 15;
    const int tid = threadIdx.x;
    const int s  = blockIdx.x * 128 + (tid & 127);
    const int cg = tid >> 7;              /* 0..3 -> 8 c each */

    __shared__ float qd[CC][DH];
    for (int i = tid; i < CC * DH; i += 512) {
        int c = i >> 6, d = i & 63;
        qd[c][d] = q_down[c * DM + h * DH + d] * QSCALE;
    }
    __syncthreads();

    const float4* kp = (const float4*)(kd + (size_t)s * (BATCH * DM) + b * DM + h * DH);
    float4 kr[16];
    #pragma unroll
    for (int d4 = 0; d4 < 16; d4++) kr[d4] = kp[d4];

    #pragma unroll
    for (int cc = 0; cc < 8; cc++) {
        const int c = cg * 8 + cc;
        float acc = 0.f;
        #pragma unroll
        for (int d4 = 0; d4 < 16; d4++) {
            const float4 q = *(const float4*)&qd[c][d4 * 4];
            acc += q.x * kr[d4].x;
            acc += q.y * kr[d4].y;
            acc += q.z * kr[d4].z;
            acc += q.w * kr[d4].w;
        }
        down[((size_t)bh * CC + c) * S_LEN + s] = acc;
    }
}

/* ------------------------------------------------------------------ */
__global__ __launch_bounds__(128) void maxexp_kernel(
    const float* __restrict__ down, float* __restrict__ wmat)
{
    const int bc = blockIdx.x;
    const int bh = bc >> 5;
    const int c  = bc & 31;
    const int t  = threadIdx.x;
    const float* row = down + (size_t)bc * S_LEN;

    float mx = -3.0e38f;
    for (int i = t; i < S_LEN; i += 128) mx = fmaxf(mx, row[i]);

    __shared__ float red[128];
    red[t] = mx;
    __syncthreads();
    for (int st = 64; st > 0; st >>= 1) {
        if (t < st) red[t] = fmaxf(red[t], red[t + st]);
        __syncthreads();
    }
    mx = red[0];

    for (int i = t; i < S_LEN; i += 128)
        wmat[((size_t)bh * S_LEN + i) * CC + c] = __expf(row[i] - mx);
}

/* ------------------------------------------------------------------ */
__global__ __launch_bounds__(256) void chunk_sum_kernel(
    const float* __restrict__ vk, const float* __restrict__ vv,
    const float* __restrict__ wmat,
    float* __restrict__ stK, float* __restrict__ stV, float* __restrict__ stN)
{
    const int bc = blockIdx.x;
    const int bh = bc >> 5, ch = bc & 31;
    const int b  = bh >> 4, h = bh & 15;
    const int tid = threadIdx.x, lane = tid & 31, warp = tid >> 5;
    const int s0 = ch * CS;

    __shared__ float vks[CS][DH];
    __shared__ float vvs[CS][DH];
    __shared__ float ws[CS][CC];

    const size_t base_off = (size_t)b * DM + h * DH;

    for (int i = tid; i < CS * DH; i += 256) {
        int r = i >> 6, d = i & 63;
        size_t g = (size_t)(s0 + r) * (BATCH * DM) + base_off + d;
        vks[r][d] = vk[g];
        vvs[r][d] = vv[g];
    }
    for (int i = tid; i < CS * CC; i += 256) {
        int r = i >> 5, c = i & 31;
        ws[r][c] = wmat[((size_t)bh * S_LEN + s0 + r) * CC + c];
    }
    __syncthreads();

    float Ak[8], Av[8];
    #pragma unroll
    for (int j = 0; j < 8; j++) { Ak[j] = 0.f; Av[j] = 0.f; }
    float norm = 0.f;
    for (int i = 0; i < CS; i++) {
        const float wvv = ws[i][lane];
        norm += wvv;
        #pragma unroll
        for (int j = 0; j < 8; j++) {
            Ak[j] += wvv * vks[i][warp * 8 + j];
            Av[j] += wvv * vvs[i][warp * 8 + j];
        }
    }

    const size_t so = ((size_t)bh * NCH + ch) * 2048 + lane * 64 + warp * 8;
    #pragma unroll
    for (int j = 0; j < 8; j++) { stK[so + j] = Ak[j]; stV[so + j] = Av[j]; }
    if (warp == 0) stN[((size_t)bh * NCH + ch) * 32 + lane] = norm;
}

/* ------------------------------------------------------------------ */
__global__ __launch_bounds__(256) void scan_kernel(
    float* __restrict__ stK, float* __restrict__ stV, float* __restrict__ stN)
{
    const int bh = blockIdx.x, part = blockIdx.y, tid = threadIdx.x;
    if (part < 16) {
        float* base = ((part < 8) ? stK : stV) + (size_t)bh * NCH * 2048;
        const int idx = (part & 7) * 256 + tid;
        float a = 0.f;
        #pragma unroll
        for (int j = 0; j < NCH; j++) {
            float t = base[j * 2048 + idx];
            base[j * 2048 + idx] = a;
            a += t;
        }
    } else if (tid < 32) {
        float* bN = stN + (size_t)bh * NCH * 32;
        float a = 0.f;
        #pragma unroll
        for (int j = 0; j < NCH; j++) {
            float t = bN[j * 32 + tid]; bN[j * 32 + tid] = a; a += t;
        }
    }
}

/* ------------------------------------------------------------------ */
#define TP36 36
#define DP68 68
#define O_Q    0
#define O_VKT  2080
#define O_VVS  4384
#define O_AKT  6560
#define O_AVS  8864
#define O_W    11040
#define O_WT   12192
#define O_P    13344
#define O_C    14496
#define O_NC   15648
#define O_N0   16800
#define ACH_SMEM ((O_N0 + 32) * 4)

__global__ __launch_bounds__(256) void attn_chunk_kernel(
    const float* __restrict__ qu, const float* __restrict__ vkm,
    const float* __restrict__ vvm, const float* __restrict__ wmat,
    const float* __restrict__ stK, const float* __restrict__ stV,
    const float* __restrict__ stN,
    __nv_bfloat16* __restrict__ ath, __nv_bfloat16* __restrict__ atl)
{
    extern __shared__ float sh[];
    const int bc = blockIdx.x, bh = bc >> 5, ch = bc & 31;
    const int b = bh >> 4, h = bh & 15;
    const int tid = threadIdx.x;
    const int s0 = ch * CS;
    const size_t base = (size_t)b * DM + h * DH;

    for (int i = tid; i < 32 * 64; i += 256) {
        int r = i >> 6, d = i & 63;
        size_t g = (size_t)(s0 + r) * (BATCH * DM) + base + d;
        sh[O_Q   + r * 65 + d]   = qu[g] * QSCALE;
        sh[O_VKT + d * TP36 + r] = vkm[g];
        sh[O_VVS + r * DP68 + d] = vvm[g];
    }
    const size_t st0 = ((size_t)bh * NCH + ch) * 2048;
    for (int i = tid; i < 32 * 64; i += 256) {
        int c = i >> 6, d = i & 63;
        sh[O_AKT + d * TP36 + c] = stK[st0 + i];
        sh[O_AVS + c * DP68 + d] = stV[st0 + i];
    }
    for (int i = tid; i < 32 * 32; i += 256) {
        int r = i >> 5, c = i & 31;
        float wv = wmat[((size_t)bh * S_LEN + s0 + r) * CC + c];
        sh[O_W  + r * TP36 + c] = wv;
        sh[O_WT + c * TP36 + r] = wv;
    }
    if (tid < 32) sh[O_N0 + tid] = stN[((size_t)bh * NCH + ch) * 32 + tid];
    __syncthreads();

    const int s  = tid >> 3;
    const int q4 = (tid & 7) * 4;

    if (tid < 32) {
        float run = sh[O_N0 + tid];
        for (int ss = 0; ss < 32; ss++) {
            run += sh[O_W + ss * TP36 + tid];
            sh[O_NC + ss * TP36 + tid] = run;
        }
    }

    /* M1: P[s][t] = Q[s]·VK[t], mask t<=s */
    {
        float c0 = 0, c1 = 0, c2 = 0, c3 = 0;
        #pragma unroll 8
        for (int d = 0; d < 64; d++) {
            const float a = sh[O_Q + s * 65 + d];
            const float4 bv = *(const float4*)&sh[O_VKT + d * TP36 + q4];
            c0 += a * bv.x; c1 += a * bv.y; c2 += a * bv.z; c3 += a * bv.w;
        }
        sh[O_P + s * TP36 + q4 + 0] = (q4 + 0 <= s) ? c0 : 0.f;
        sh[O_P + s * TP36 + q4 + 1] = (q4 + 1 <= s) ? c1 : 0.f;
        sh[O_P + s * TP36 + q4 + 2] = (q4 + 2 <= s) ? c2 : 0.f;
        sh[O_P + s * TP36 + q4 + 3] = (q4 + 3 <= s) ? c3 : 0.f;
    }
    __syncthreads();

    /* M2: C[s][c] = (Q[s]·AK[c] + sum_t P[s][t]·W[t][c]) / NC[s][c] */
    {
        float c0 = 0, c1 = 0, c2 = 0, c3 = 0;
        #pragma unroll 8
        for (int d = 0; d < 64; d++) {
            const float a = sh[O_Q + s * 65 + d];
            const float4 bv = *(const float4*)&sh[O_AKT + d * TP36 + q4];
            c0 += a * bv.x; c1 += a * bv.y; c2 += a * bv.z; c3 += a * bv.w;
        }
        #pragma unroll 8
        for (int t = 0; t < 32; t++) {
            const float a = sh[O_P + s * TP36 + t];
            const float4 bv = *(const float4*)&sh[O_W + t * TP36 + q4];
            c0 += a * bv.x; c1 += a * bv.y; c2 += a * bv.z; c3 += a * bv.w;
        }
        const float4 nc = *(const float4*)&sh[O_NC + s * TP36 + q4];
        sh[O_C + s * TP36 + q4 + 0] = c0 / nc.x;
        sh[O_C + s * TP36 + q4 + 1] = c1 / nc.y;
        sh[O_C + s * TP36 + q4 + 2] = c2 / nc.z;
        sh[O_C + s * TP36 + q4 + 3] = c3 / nc.w;
    }
    __syncthreads();

    /* softmax over c per row; coeff = p / (sum * ncum) */
    {
        const int lane = tid & 31, w = tid >> 5;
        #pragma unroll
        for (int r = w * 4; r < w * 4 + 4; r++) {
            float v = sh[O_C + r * TP36 + lane];
            float mx = v;
            #pragma unroll
            for (int o = 16; o > 0; o >>= 1)
                mx = fmaxf(mx, __shfl_xor_sync(0xFFFFFFFFu, mx, o));
            float e = __expf(v - mx);
            float se = e;
            #pragma unroll
            for (int o = 16; o > 0; o >>= 1)
                se += __shfl_xor_sync(0xFFFFFFFFu, se, o);
            sh[O_C + r * TP36 + lane] = e / (se * sh[O_NC + r * TP36 + lane]);
        }
    }
    __syncthreads();

    /* M4: G[s][t] = sum_c C[s][c]·W[t][c], mask t<=s (into P) */
    {
        float c0 = 0, c1 = 0, c2 = 0, c3 = 0;
        #pragma unroll 8
        for (int c = 0; c < 32; c++) {
            const float a = sh[O_C + s * TP36 + c];
            const float4 bv = *(const float4*)&sh[O_WT + c * TP36 + q4];
            c0 += a * bv.x; c1 += a * bv.y; c2 += a * bv.z; c3 += a * bv.w;
        }
        sh[O_P + s * TP36 + q4 + 0] = (q4 + 0 <= s) ? c0 : 0.f;
        sh[O_P + s * TP36 + q4 + 1] = (q4 + 1 <= s) ? c1 : 0.f;
        sh[O_P + s * TP36 + q4 + 2] = (q4 + 2 <= s) ? c2 : 0.f;
        sh[O_P + s * TP36 + q4 + 3] = (q4 + 3 <= s) ? c3 : 0.f;
    }
    __syncthreads();

    /* M5: out[s][d] = sum_c C[s][c]·AV[c][d] + sum_t G[s][t]·VV[t][d] */
    #pragma unroll
    for (int half = 0; half < 2; half++) {
        const int dd = q4 + half * 32;
        float o0 = 0, o1 = 0, o2 = 0, o3 = 0;
        #pragma unroll 8
        for (int c = 0; c < 32; c++) {
            const float a = sh[O_C + s * TP36 + c];
            const float4 bv = *(const float4*)&sh[O_AVS + c * DP68 + dd];
            o0 += a * bv.x; o1 += a * bv.y; o2 += a * bv.z; o3 += a * bv.w;
        }
        #pragma unroll 8
        for (int t = 0; t < 32; t++) {
            const float g = sh[O_P + s * TP36 + t];
            const float4 bv = *(const float4*)&sh[O_VVS + t * DP68 + dd];
            o0 += g * bv.x; o1 += g * bv.y; o2 += g * bv.z; o3 += g * bv.w;
        }
        const size_t gi = (size_t)(s0 + s) * (BATCH * DM) + base + dd;
        float vals[4] = {o0, o1, o2, o3};
        #pragma unroll
        for (int j = 0; j < 4; j++) {
            __nv_bfloat16 hb = __float2bfloat16(vals[j]);
            ath[gi + j] = hb;
            atl[gi + j] = __float2bfloat16(vals[j] - __bfloat162float(hb));
        }
    }
}

/* ------------------------------------------------------------------ */
extern "C" void kernel_launch(void* const* d_in, const int* in_sizes, int n_in,
                              void* d_out, int out_size)
{
    (void)in_sizes; (void)n_in; (void)out_size;
    const float* x      = (const float*)d_in[0];
    const float* q_down = (const float*)d_in[1];
    const float* Wq     = (const float*)d_in[2];
    const float* bq     = (const float*)d_in[3];
    const float* Wk     = (const float*)d_in[4];
    const float* bk     = (const float*)d_in[5];
    const float* Wv     = (const float*)d_in[6];
    const float* bv     = (const float*)d_in[7];
    const float* Wo     = (const float*)d_in[8];
    const float* bo     = (const float*)d_in[9];
    float* out = (float*)d_out;

    float* scr = nullptr;
    cudaGetSymbolAddress((void**)&scr, g_scratch);
    float* g_qu  = scr + OFF_QU;
    float* g_kd  = scr + OFF_KD;
    float* g_vdk = scr + OFF_VDK;
    float* g_vdv = scr + OFF_VDV;
    float* g_dn  = scr + OFF_DOWN;
    float* g_w   = scr + OFF_W;
    float* g_stk = scr + OFF_STK;
    float* g_stv = scr + OFF_STV;
    float* g_stn = scr + OFF_STN;

    __nv_bfloat16* xh  = (__nv_bfloat16*)(scr + OFF_XH);
    __nv_bfloat16* xl  = (__nv_bfloat16*)(scr + OFF_XL);
    __nv_bfloat16* wqh = (__nv_bfloat16*)(scr + OFF_WQH);
    __nv_bfloat16* wql = (__nv_bfloat16*)(scr + OFF_WQL);
    __nv_bfloat16* wkh = (__nv_bfloat16*)(scr + OFF_WKH);
    __nv_bfloat16* wkl = (__nv_bfloat16*)(scr + OFF_WKL);
    __nv_bfloat16* wvh = (__nv_bfloat16*)(scr + OFF_WVH);
    __nv_bfloat16* wvl = (__nv_bfloat16*)(scr + OFF_WVL);
    __nv_bfloat16* woh = (__nv_bfloat16*)(scr + OFF_WOH);
    __nv_bfloat16* wol = (__nv_bfloat16*)(scr + OFF_WOL);
    __nv_bfloat16* vdh = (__nv_bfloat16*)(scr + OFF_VDH);
    __nv_bfloat16* vdl = (__nv_bfloat16*)(scr + OFF_VDL);
    __nv_bfloat16* ath = (__nv_bfloat16*)(scr + OFF_ATH);
    __nv_bfloat16* atl = (__nv_bfloat16*)(scr + OFF_ATL);

    cudaFuncSetAttribute(gemm_bf16_bias,
                         cudaFuncAttributeMaxDynamicSharedMemorySize, GEMM_SMEM);
    cudaFuncSetAttribute(attn_chunk_kernel,
                         cudaFuncAttributeMaxDynamicSharedMemorySize, ACH_SMEM);

    const int n4x = MROWS * DM / 4;
    const int n4w = DM * DM / 4;

    CvtSeg cs0 = {(const float4*)x,  (uint2*)xh,  (uint2*)xl,  n4x};
    CvtSeg cs1 = {(const float4*)Wq, (uint2*)wqh, (uint2*)wql, n4w};
    CvtSeg cs2 = {(const float4*)Wk, (uint2*)wkh, (uint2*)wkl, n4w};
    CvtSeg cs3 = {(const float4*)Wv, (uint2*)wvh, (uint2*)wvl, n4w};
    CvtSeg cs4 = {(const float4*)Wo, (uint2*)woh, (uint2*)wol, n4w};
    cvt_multi_kernel<<<dim3(n4x / 256, 5), 256>>>(cs0, cs1, cs2, cs3, cs4);

    GemmArgs aq  = {wqh, wql, bq, g_qu,   nullptr, nullptr};
    GemmArgs ak  = {wkh, wkl, bk, g_kd,   nullptr, nullptr};
    GemmArgs av  = {wvh, wvl, bv, nullptr, vdh, vdl};     /* vd: planes only */
    GemmArgs a2k = {wkh, wkl, bk, g_vdk,  nullptr, nullptr};
    GemmArgs a2v = {wvh, wvl, bv, g_vdv,  nullptr, nullptr};
    GemmArgs ao  = {woh, wol, bo, out,    nullptr, nullptr};

    dim3 gg(DM / 128, MROWS / 128);   /* (8, 16) */

    gemm_bf16_bias<<<dim3(gg.x, gg.y, 3), 512, GEMM_SMEM>>>(xh, xl, aq, ak, av);

    gemm_bf16_bias<<<dim3(gg.x, gg.y, 2), 512, GEMM_SMEM>>>(vdh, vdl, a2k, a2v, a2v);

    down_kernel<<<dim3(S_LEN / 128, BATCH * NH), 512>>>(q_down, g_kd, g_dn);
    maxexp_kernel<<<BATCH * NH * CC, 128>>>(g_dn, g_w);

    chunk_sum_kernel<<<BATCH * NH * NCH, 256>>>(g_vdk, g_vdv, g_w,
                                                g_stk, g_stv, g_stn);
    scan_kernel<<<dim3(BATCH * NH, 17), 256>>>(g_stk, g_stv, g_stn);
    attn_chunk_kernel<<<BATCH * NH * NCH, 256, ACH_SMEM>>>(
        g_qu, g_vdk, g_vdv, g_w, g_stk, g_stv, g_stn, ath, atl);

    gemm_bf16_bias<<<dim3(gg.x, gg.y, 1), 512, GEMM_SMEM>>>(ath, atl, ao, ao, ao);
}